// round 14
// baseline (speedup 1.0000x reference)
#include <cuda_runtime.h>
#include <math.h>
#include <cstdint>

#define Bn   4
#define Nn   1024
#define Dn   1024
#define Hn   16
#define DHn  64

typedef unsigned short ushort_t;

// ---------------------------------------------------------------------------
// Scratch (__device__ globals)
// Interleaved split-plane layout per operand: [row][kchunk][plane(3)][16] bf16
// ---------------------------------------------------------------------------
__device__ __align__(16) ushort_t g_x3[(size_t)4096 * 64 * 48];     // 25.2 MB
__device__ __align__(16) ushort_t g_w3[(size_t)3072 * 64 * 48];     // 18.9 MB
__device__ __align__(16) ushort_t g_q3[(size_t)64 * 1024 * 4 * 48]; // 25.2 MB
__device__ __align__(16) ushort_t g_k3[(size_t)64 * 1024 * 4 * 48]; // 25.2 MB
__device__ float g_v[(size_t)4096 * 1024];                          // 16.8 MB
__device__ float g_s[(size_t)64 * 1024 * 1024];                     // 268.4 MB

// ---------------------------------------------------------------------------
// helpers
// ---------------------------------------------------------------------------
__device__ __forceinline__ uint32_t s2u(const void* p) {
    uint32_t a;
    asm("{ .reg .u64 t; cvta.to.shared.u64 t, %1; cvt.u32.u64 %0, t; }" : "=r"(a) : "l"(p));
    return a;
}
__device__ __forceinline__ void cp16cg(uint32_t s, const void* g) {
    asm volatile("cp.async.cg.shared.global [%0], [%1], 16;" :: "r"(s), "l"(g));
}
#define CP_COMMIT() asm volatile("cp.async.commit_group;" ::: "memory")
#define CP_WAIT(n)  asm volatile("cp.async.wait_group %0;" :: "n"(n) : "memory")

// 3-way bf16 split: f = b0 + b1 + b2  (deterministic; identical to R4..R13)
__device__ __forceinline__ void split3(float f, ushort_t& u0, ushort_t& u1, ushort_t& u2) {
    ushort_t h0;
    asm("cvt.rn.bf16.f32 %0, %1;" : "=h"(h0) : "f"(f));
    float f0; asm("cvt.f32.bf16 %0, %1;" : "=f"(f0) : "h"(h0));
    float r1 = f - f0;
    ushort_t h1;
    asm("cvt.rn.bf16.f32 %0, %1;" : "=h"(h1) : "f"(r1));
    float f1; asm("cvt.f32.bf16 %0, %1;" : "=f"(f1) : "h"(h1));
    float r2 = r1 - f1;
    ushort_t h2;
    asm("cvt.rn.bf16.f32 %0, %1;" : "=h"(h2) : "f"(r2));
    u0 = h0; u1 = h1; u2 = h2;
}
__device__ __forceinline__ void splitpack(float fx, float fy,
                                          uint32_t& r0, uint32_t& r1, uint32_t& r2) {
    ushort_t a0, a1, a2, b0, b1, b2;
    split3(fx, a0, a1, a2);
    split3(fy, b0, b1, b2);
    r0 = (uint32_t)a0 | ((uint32_t)b0 << 16);
    r1 = (uint32_t)a1 | ((uint32_t)b1 << 16);
    r2 = (uint32_t)a2 | ((uint32_t)b2 << 16);
}
__device__ __forceinline__ void mma16(float* c, const uint32_t* a, uint32_t b0, uint32_t b1) {
    asm volatile(
        "mma.sync.aligned.m16n8k16.row.col.f32.bf16.bf16.f32 "
        "{%0,%1,%2,%3}, {%4,%5,%6,%7}, {%8,%9}, {%0,%1,%2,%3};"
        : "+f"(c[0]), "+f"(c[1]), "+f"(c[2]), "+f"(c[3])
        : "r"(a[0]), "r"(a[1]), "r"(a[2]), "r"(a[3]), "r"(b0), "r"(b1));
}
__device__ __forceinline__ void ldsm4(uint32_t& r0, uint32_t& r1, uint32_t& r2, uint32_t& r3,
                                      uint32_t addr) {
    asm volatile("ldmatrix.sync.aligned.m8n8.x4.shared.b16 {%0,%1,%2,%3}, [%4];"
                 : "=r"(r0), "=r"(r1), "=r"(r2), "=r"(r3) : "r"(addr));
}

// write split planes of a float pair into interleaved layout
__device__ __forceinline__ void store3(ushort_t* cat, size_t rowIdx, int nch, int d,
                                       float c0, float c1) {
    uint32_t r0, r1, r2;
    splitpack(c0, c1, r0, r1, r2);
    uint32_t* pb = (uint32_t*)cat;
    const int kc = d >> 4, wi = (d & 15) >> 1;
    const size_t base = (rowIdx * nch + kc) * 3;
    pb[(base + 0) * 8 + wi] = r0;
    pb[(base + 1) * 8 + wi] = r1;
    pb[(base + 2) * 8 + wi] = r2;
}

// ---------------------------------------------------------------------------
// Prep: x -> g_x3, [Wq;Wkv] -> g_w3 (one thread = one float2)
// ---------------------------------------------------------------------------
__global__ __launch_bounds__(256) void prep_kernel(
    const float* __restrict__ x, const float* __restrict__ Wq, const float* __restrict__ Wkv)
{
    const int PX = 4096 * 512;
    const int PW = 3072 * 512;
    int idx = blockIdx.x * 256 + threadIdx.x;
    if (idx >= PX + PW) return;

    if (idx < PX) {
        int m = idx >> 9, kp = idx & 511;
        float2 v = *(const float2*)(x + (size_t)m * 1024 + kp * 2);
        store3(g_x3, (size_t)m, 64, kp * 2, v.x, v.y);
    } else {
        int j = idx - PX;
        int n = j >> 9, kp = j & 511;
        const float* src = (n < 1024) ? (Wq + (size_t)n * 1024)
                                      : (Wkv + (size_t)(n - 1024) * 1024);
        float2 v = *(const float2*)(src + kp * 2);
        store3(g_w3, (size_t)n, 64, kp * 2, v.x, v.y);
    }
}

// ---------------------------------------------------------------------------
// shared GEMM bits
// ---------------------------------------------------------------------------
#define SROW  24
#define SPL   (128 * SROW)         // 3072 shorts per plane
#define NSTG  3
#define SOP   (NSTG * 3 * SPL)     // per operand: 27648 shorts
#define SMEMB (2 * SOP * 2)        // 110592 bytes
#define STG_STRIDE_B (3 * SPL * 2) // 18432 bytes per stage

struct Frag { float acc[2][8][4]; };

// term t -> (A plane, B plane): a0b0, a0b1, a1b0, a1b1, a0b2, a2b0
#define DO_TERMS(ACCSEL)                                                     \
    {                                                                        \
        constexpr int TA[6] = {0, 0, 1, 1, 0, 2};                            \
        constexpr int TB[6] = {0, 1, 0, 1, 2, 0};                            \
        _Pragma("unroll")                                                    \
        for (int t = 0; t < 6; t++) {                                        \
            const int ap = TA[t], bp = TB[t];                                \
            _Pragma("unroll")                                                \
            for (int q = 0; q < 2; q++)                                      \
                _Pragma("unroll")                                            \
                for (int sub = 0; sub < 2; sub++)                            \
                    _Pragma("unroll")                                        \
                    for (int mt = 0; mt < 2; mt++)                           \
                        mma16(F.acc[mt][ACCSEL],                             \
                              Af[mt][ap], Bm[q][bp][sub], Bm[q][bp][sub+2]); \
        }                                                                    \
    }

// Remapped thread->transfer assignment: row = tid&127, seg = (tid>>7)+2*(i%3),
// side compile-time per unrolled i. Same copy set / same smem contents as the
// div-chain version (bit-exact); ~3 instr per transfer, no extra registers.
__device__ __forceinline__ void ld_stage(
    ushort_t* sm, int stage,
    const ushort_t* __restrict__ A, int lda,
    const ushort_t* __restrict__ B, int ldb, int kt)
{
    const int row = threadIdx.x & 127;
    const int s   = threadIdx.x >> 7;   // 0 or 1
#pragma unroll
    for (int i = 0; i < 6; i++) {
        const bool sideB = (i >= 3);
        const int seg  = s + 2 * (sideB ? (i - 3) : i);
        const int p    = seg >> 1;
        const int half = seg & 1;
        const ushort_t* src = (sideB ? B + (size_t)row * ldb
                                     : A + (size_t)row * lda) + kt * 48 + seg * 8;
        uint32_t dst = s2u(&sm[(sideB ? SOP : 0) + ((stage * 3 + p) * 128 + row) * SROW + half * 8]);
        cp16cg(dst, src);
    }
}

__device__ __forceinline__ void gemm_planes(
    ushort_t* sm,
    const ushort_t* __restrict__ A, int lda,
    const ushort_t* __restrict__ B, int ldb,
    int NK, Frag& F)
{
    const int tid  = threadIdx.x;
    const int lane = tid & 31;
    const int wid  = tid >> 5;
    const int wm   = wid & 3;
    const int wn   = wid >> 2;

    const int lrow = (lane & 7) + ((lane >> 3) & 1) * 8;
    const int lhal = lane >> 4;

    const uint32_t smb = s2u(sm);
    uint32_t aoff[2], boff[4];
#pragma unroll
    for (int mt = 0; mt < 2; mt++)
        aoff[mt] = smb + ((wm * 32 + mt * 16 + lrow) * SROW + lhal * 8) * 2;
#pragma unroll
    for (int ntp = 0; ntp < 4; ntp++)
        boff[ntp] = smb + SOP * 2 + ((wn * 64 + ntp * 16 + lrow) * SROW + lhal * 8) * 2;

#pragma unroll
    for (int mt = 0; mt < 2; mt++)
#pragma unroll
        for (int nt = 0; nt < 8; nt++)
#pragma unroll
            for (int r = 0; r < 4; r++) F.acc[mt][nt][r] = 0.f;

#pragma unroll
    for (int p = 0; p < NSTG - 1; p++) {
        ld_stage(sm, p, A, lda, B, ldb, p);
        CP_COMMIT();
    }

    for (int kt = 0; kt < NK; kt++) {
        const bool more = (kt + NSTG - 1 < NK);
        if (more) { CP_WAIT(1); } else { CP_WAIT(0); }
        __syncthreads();
        if (more) {
            ld_stage(sm, (kt + NSTG - 1) % NSTG, A, lda, B, ldb, kt + NSTG - 1);
            CP_COMMIT();
        }

        const int buf = kt % 3;
        const uint32_t pbase = (uint32_t)(buf * 3) * SPL * 2;

        uint32_t Af[2][3][4];
#pragma unroll
        for (int mt = 0; mt < 2; mt++)
#pragma unroll
            for (int p = 0; p < 3; p++)
                ldsm4(Af[mt][p][0], Af[mt][p][1], Af[mt][p][2], Af[mt][p][3],
                      aoff[mt] + pbase + p * SPL * 2);

#pragma unroll
        for (int hp = 0; hp < 2; hp++) {
            uint32_t Bm[2][3][4];
#pragma unroll
            for (int q = 0; q < 2; q++)
#pragma unroll
                for (int p = 0; p < 3; p++)
                    ldsm4(Bm[q][p][0], Bm[q][p][1], Bm[q][p][2], Bm[q][p][3],
                          boff[hp * 2 + q] + pbase + p * SPL * 2);
            DO_TERMS((hp * 2 + q) * 2 + sub)
        }
    }
    __syncthreads();
}

// ---------------------------------------------------------------------------
// Kernel 1: proj  Y[4096,3072] = x @ [Wq;Wkv]^T
// ---------------------------------------------------------------------------
__global__ __launch_bounds__(256, 2) void proj_tc()
{
    extern __shared__ __align__(16) ushort_t smp[];

    const int m0 = blockIdx.y * 128;
    const int n0 = blockIdx.x * 128;

    Frag F;
    gemm_planes(smp, g_x3 + (size_t)m0 * 3072, 3072,
                g_w3 + (size_t)n0 * 3072, 3072, 64, F);

    const int lane = threadIdx.x & 31;
    const int wid  = threadIdx.x >> 5;
    const int wm = wid & 3, wn = wid >> 2;

#pragma unroll
    for (int mt = 0; mt < 2; mt++)
#pragma unroll
        for (int nt = 0; nt < 8; nt++) {
            const int r  = m0 + wm * 32 + mt * 16 + (lane >> 2);
            const int cc = n0 + wn * 64 + nt * 8 + (lane & 3) * 2;
            const float* c = F.acc[mt][nt];
            if (n0 >= 2048) {
                *(float2*)(g_v + (size_t)r * 1024 + (cc - 2048)) = make_float2(c[0], c[1]);
                *(float2*)(g_v + (size_t)(r + 8) * 1024 + (cc - 2048)) = make_float2(c[2], c[3]);
            } else {
                const bool isq = (n0 < 1024);
                const int nn = isq ? cc : cc - 1024;
                const int h = nn >> 6, d = nn & 63;
                const int bidx = r >> 10;
                ushort_t* cat = isq ? g_q3 : g_k3;
                const size_t row0 = (size_t)(bidx * 16 + h) * 1024 + (r & 1023);
                const size_t row1 = (size_t)(bidx * 16 + h) * 1024 + ((r + 8) & 1023);
                store3(cat, row0, 4, d, c[0], c[1]);
                store3(cat, row1, 4, d, c[2], c[3]);
            }
        }
}

// ---------------------------------------------------------------------------
// Kernel 2: score  S[b,h] = (q_h k_h^T)/32
// 4 j-tiles per CTA: A (q tile, all 4 chunks) resident in smem, B (k) streams
// through a 2-stage double buffer. Per output tile: same 4-chunk, same MMA
// order as R4..R13 (bit-exact).
// ---------------------------------------------------------------------------
__device__ __forceinline__ void ld_Bstage(
    ushort_t* smB, int stage, const ushort_t* __restrict__ B, int kt)
{
    const int row = threadIdx.x & 127;
    const int s   = threadIdx.x >> 7;   // 0 or 1
#pragma unroll
    for (int i = 0; i < 3; i++) {
        const int seg  = s + 2 * i;
        const int p    = seg >> 1;
        const int half = seg & 1;
        cp16cg(s2u(&smB[((stage * 3 + p) * 128 + row) * SROW + half * 8]),
               B + (size_t)row * 192 + kt * 48 + seg * 8);
    }
}

__global__ __launch_bounds__(256, 2) void score_tc()
{
    extern __shared__ __align__(16) ushort_t smp[];
    ushort_t* smA = smp;                 // [4 chunks][3 planes][128][SROW]
    ushort_t* smB = smp + 12 * SPL;      // [2 stages][3 planes][128][SROW]

    const int jt0 = blockIdx.x * 4;
    const int it  = blockIdx.y;
    const int z   = blockIdx.z;

    const ushort_t* Ab = g_q3 + ((size_t)z * 1024 + it * 128) * 192;
    const ushort_t* Bz = g_k3 + (size_t)z * 1024 * 192;

    // prologue: A all 4 chunks + B stage for s=0 (one cp.async group)
    for (int t = threadIdx.x; t < 3072; t += 256) {
        const int c    = t / 768;
        const int rr   = t - c * 768;
        const int row  = rr / 6;
        const int seg  = rr - row * 6;
        const int p    = seg >> 1;
        const int half = seg & 1;
        cp16cg(s2u(&smA[((c * 3 + p) * 128 + row) * SROW + half * 8]),
               Ab + (size_t)row * 192 + c * 48 + seg * 8);
    }
    ld_Bstage(smB, 0, Bz + (size_t)(jt0 * 128) * 192, 0);
    CP_COMMIT();

    const int tid  = threadIdx.x;
    const int lane = tid & 31;
    const int wid  = tid >> 5;
    const int wm   = wid & 3;
    const int wn   = wid >> 2;
    const int lrow = (lane & 7) + ((lane >> 3) & 1) * 8;
    const int lhal = lane >> 4;

    uint32_t aoff[2], boff[4];
#pragma unroll
    for (int mt = 0; mt < 2; mt++)
        aoff[mt] = s2u(smA) + ((wm * 32 + mt * 16 + lrow) * SROW + lhal * 8) * 2;
#pragma unroll
    for (int ntp = 0; ntp < 4; ntp++)
        boff[ntp] = s2u(smB) + ((wn * 64 + ntp * 16 + lrow) * SROW + lhal * 8) * 2;

    Frag F;
#pragma unroll
    for (int mt = 0; mt < 2; mt++)
#pragma unroll
        for (int nt = 0; nt < 8; nt++)
#pragma unroll
            for (int r = 0; r < 4; r++) F.acc[mt][nt][r] = 0.f;

    const float scale = 0.03125f;

    for (int s = 0; s < 16; s++) {
        CP_WAIT(0);
        __syncthreads();
        if (s + 1 < 16) {
            const int jtn = jt0 + (s + 1) / 4;
            const int ktn = (s + 1) & 3;
            ld_Bstage(smB, (s + 1) & 1, Bz + (size_t)(jtn * 128) * 192, ktn);
            CP_COMMIT();
        }

        const int kt = s & 3;
        const uint32_t abase = (uint32_t)(kt * 3) * SPL * 2;
        const uint32_t bbase = (uint32_t)((s & 1) * 3) * SPL * 2;

        uint32_t Af[2][3][4];
#pragma unroll
        for (int mt = 0; mt < 2; mt++)
#pragma unroll
            for (int p = 0; p < 3; p++)
                ldsm4(Af[mt][p][0], Af[mt][p][1], Af[mt][p][2], Af[mt][p][3],
                      aoff[mt] + abase + p * SPL * 2);

#pragma unroll
        for (int hp = 0; hp < 2; hp++) {
            uint32_t Bm[2][3][4];
#pragma unroll
            for (int q = 0; q < 2; q++)
#pragma unroll
                for (int p = 0; p < 3; p++)
                    ldsm4(Bm[q][p][0], Bm[q][p][1], Bm[q][p][2], Bm[q][p][3],
                          boff[hp * 2 + q] + bbase + p * SPL * 2);
            DO_TERMS((hp * 2 + q) * 2 + sub)
        }

        if (kt == 3) {
            const int jt = jt0 + (s >> 2);
#pragma unroll
            for (int mt = 0; mt < 2; mt++)
#pragma unroll
                for (int nt = 0; nt < 8; nt++) {
                    int r  = it * 128 + wm * 32 + mt * 16 + (lane >> 2);
                    int cc = jt * 128 + wn * 64 + nt * 8 + (lane & 3) * 2;
                    float* base = g_s + ((size_t)z * Nn + r) * Nn + cc;
                    float* c = F.acc[mt][nt];
                    __stcs((float2*)base, make_float2(c[0] * scale, c[1] * scale));
                    __stcs((float2*)(base + 8 * Nn), make_float2(c[2] * scale, c[3] * scale));
                    c[0] = 0.f; c[1] = 0.f; c[2] = 0.f; c[3] = 0.f;
                }
        }
    }
}

// ---------------------------------------------------------------------------
// Kernel 3: attn — R12 version (unchanged).
// ---------------------------------------------------------------------------
__global__ __launch_bounds__(512) void attn_kernel(
    const float* __restrict__ Wt,
    const float* __restrict__ ln_g,
    const float* __restrict__ ln_b,
    float* __restrict__ out)
{
    extern __shared__ float sm[];
    float* sw   = sm;                 // [16][1024] raw exp values
    float* swt  = sm + Hn * Nn;       // [256]
    float* sg   = swt + 256;          // [16]
    float* sb   = sg + 16;            // [16]
    float* ssum = sb + 16;            // [16]

    const int tid = threadIdx.x;
    const int i   = blockIdx.x;
    const int b   = blockIdx.y;

#pragma unroll
    for (int f = tid; f < Hn * Nn / 4; f += 512) {
        int h = f >> 8;
        int j4 = (f & 255) * 4;
        cp16cg(s2u(sw + h * Nn + j4),
               g_s + ((size_t)(b * Hn + h) * Nn + i) * Nn + j4);
    }
    CP_COMMIT();
    if (tid < 256) swt[tid] = Wt[tid];
    if (tid < 16) { sg[tid] = ln_g[tid]; sb[tid] = ln_b[tid]; }
    CP_WAIT(0);
    __syncthreads();

    const int warp = tid >> 5;
    const int lane = tid & 31;

    {
        float* row = sw + warp * Nn;
        float m = -INFINITY;
        for (int j = lane; j < Nn; j += 32) m = fmaxf(m, row[j]);
#pragma unroll
        for (int o = 16; o; o >>= 1) m = fmaxf(m, __shfl_xor_sync(~0u, m, o));
        float s = 0.f;
        for (int j = lane; j < Nn; j += 32) { float e = expf(row[j] - m); row[j] = e; s += e; }
#pragma unroll
        for (int o = 16; o; o >>= 1) s += __shfl_xor_sync(~0u, s, o);
        if (lane == 0) ssum[warp] = s;
    }
    __syncthreads();

    for (int j = tid; j < Nn; j += 512) {
        float wc[16];
#pragma unroll
        for (int h = 0; h < 16; h++) wc[h] = sw[h * Nn + j] / ssum[h];
        float mix[16];
        float mu = 0.f;
#pragma unroll
        for (int ho = 0; ho < 16; ho++) {
            float acc = 0.f;
#pragma unroll
            for (int h = 0; h < 16; h++) acc += swt[ho * 16 + h] * wc[h];
            mix[ho] = acc;
            mu += acc;
        }
        mu *= (1.f / 16.f);
        float var = 0.f;
#pragma unroll
        for (int ho = 0; ho < 16; ho++) { float d = mix[ho] - mu; var += d * d; }
        var *= (1.f / 16.f);
        const float denom = sqrtf(var + 1e-5f);
#pragma unroll
        for (int ho = 0; ho < 16; ho++)
            sw[ho * Nn + j] = (mix[ho] - mu) / denom * sg[ho] + sb[ho];
    }
    __syncthreads();

    {
        const int h = warp;
        float* row = sw + h * Nn;
        float bv = -INFINITY;
        int   bi = 0;
        for (int j = lane; j < Nn; j += 32) {
            float v = row[j];
            if (v > bv) { bv = v; bi = j; }
        }
#pragma unroll
        for (int o = 16; o; o >>= 1) {
            float ov = __shfl_xor_sync(~0u, bv, o);
            int   oi = __shfl_xor_sync(~0u, bi, o);
            if (ov > bv || (ov == bv && oi < bi)) { bv = ov; bi = oi; }
        }
        const float* vsrc = g_v + (size_t)(b * Nn + bi) * 1024 + h * DHn;
        float* dst = out + (size_t)(b * Nn + i) * Dn + h * DHn;
#pragma unroll
        for (int d = lane; d < DHn; d += 32) dst[d] = vsrc[d];
    }
}

// ---------------------------------------------------------------------------
extern "C" void kernel_launch(void* const* d_in, const int* in_sizes, int n_in,
                              void* d_out, int out_size)
{
    const float* x    = (const float*)d_in[0];
    const float* Wq   = (const float*)d_in[1];
    const float* Wkv  = (const float*)d_in[2];
    const float* Wt   = (const float*)d_in[3];
    const float* ln_g = (const float*)d_in[4];
    const float* ln_b = (const float*)d_in[5];
    float* out = (float*)d_out;

    const int total = (4096 + 3072) * 512;
    prep_kernel<<<(total + 255) / 256, 256>>>(x, Wq, Wkv);

    cudaFuncSetAttribute(proj_tc, cudaFuncAttributeMaxDynamicSharedMemorySize, SMEMB);
    cudaFuncSetAttribute(score_tc, cudaFuncAttributeMaxDynamicSharedMemorySize, SMEMB);

    proj_tc<<<dim3(3072 / 128, 4096 / 128), 256, SMEMB>>>();
    score_tc<<<dim3(Nn / 512, Nn / 128, Bn * Hn), 256, SMEMB>>>();

    const int asmem = (Hn * Nn + 256 + 16 + 16 + 16) * sizeof(float);
    cudaFuncSetAttribute(attn_kernel, cudaFuncAttributeMaxDynamicSharedMemorySize, asmem);
    attn_kernel<<<dim3(Nn, Bn), 512, asmem>>>(Wt, ln_g, ln_b, out);
}

// round 15
// speedup vs baseline: 1.2327x; 1.2327x over previous
#include <cuda_runtime.h>
#include <math.h>
#include <cstdint>

#define Bn   4
#define Nn   1024
#define Dn   1024
#define Hn   16
#define DHn  64

typedef unsigned short ushort_t;

// ---------------------------------------------------------------------------
// Scratch (__device__ globals)
// Interleaved split-plane layout per operand: [row][kchunk][plane(3)][16] bf16
// ---------------------------------------------------------------------------
__device__ __align__(16) ushort_t g_x3[(size_t)4096 * 64 * 48];     // 25.2 MB
__device__ __align__(16) ushort_t g_w3[(size_t)3072 * 64 * 48];     // 18.9 MB
__device__ __align__(16) ushort_t g_q3[(size_t)64 * 1024 * 4 * 48]; // 25.2 MB
__device__ __align__(16) ushort_t g_k3[(size_t)64 * 1024 * 4 * 48]; // 25.2 MB
__device__ float g_v[(size_t)4096 * 1024];                          // 16.8 MB
__device__ float g_s[(size_t)64 * 1024 * 1024];                     // 268.4 MB

// ---------------------------------------------------------------------------
// helpers
// ---------------------------------------------------------------------------
__device__ __forceinline__ uint32_t s2u(const void* p) {
    uint32_t a;
    asm("{ .reg .u64 t; cvta.to.shared.u64 t, %1; cvt.u32.u64 %0, t; }" : "=r"(a) : "l"(p));
    return a;
}
__device__ __forceinline__ void cp16cg(uint32_t s, const void* g) {
    asm volatile("cp.async.cg.shared.global [%0], [%1], 16;" :: "r"(s), "l"(g));
}
#define CP_COMMIT() asm volatile("cp.async.commit_group;" ::: "memory")
#define CP_WAIT(n)  asm volatile("cp.async.wait_group %0;" :: "n"(n) : "memory")

// 3-way bf16 split: f = b0 + b1 + b2  (deterministic; identical to R4..R14)
__device__ __forceinline__ void split3(float f, ushort_t& u0, ushort_t& u1, ushort_t& u2) {
    ushort_t h0;
    asm("cvt.rn.bf16.f32 %0, %1;" : "=h"(h0) : "f"(f));
    float f0; asm("cvt.f32.bf16 %0, %1;" : "=f"(f0) : "h"(h0));
    float r1 = f - f0;
    ushort_t h1;
    asm("cvt.rn.bf16.f32 %0, %1;" : "=h"(h1) : "f"(r1));
    float f1; asm("cvt.f32.bf16 %0, %1;" : "=f"(f1) : "h"(h1));
    float r2 = r1 - f1;
    ushort_t h2;
    asm("cvt.rn.bf16.f32 %0, %1;" : "=h"(h2) : "f"(r2));
    u0 = h0; u1 = h1; u2 = h2;
}
__device__ __forceinline__ void splitpack(float fx, float fy,
                                          uint32_t& r0, uint32_t& r1, uint32_t& r2) {
    ushort_t a0, a1, a2, b0, b1, b2;
    split3(fx, a0, a1, a2);
    split3(fy, b0, b1, b2);
    r0 = (uint32_t)a0 | ((uint32_t)b0 << 16);
    r1 = (uint32_t)a1 | ((uint32_t)b1 << 16);
    r2 = (uint32_t)a2 | ((uint32_t)b2 << 16);
}
__device__ __forceinline__ void mma16(float* c, const uint32_t* a, uint32_t b0, uint32_t b1) {
    asm volatile(
        "mma.sync.aligned.m16n8k16.row.col.f32.bf16.bf16.f32 "
        "{%0,%1,%2,%3}, {%4,%5,%6,%7}, {%8,%9}, {%0,%1,%2,%3};"
        : "+f"(c[0]), "+f"(c[1]), "+f"(c[2]), "+f"(c[3])
        : "r"(a[0]), "r"(a[1]), "r"(a[2]), "r"(a[3]), "r"(b0), "r"(b1));
}
__device__ __forceinline__ void ldsm4(uint32_t& r0, uint32_t& r1, uint32_t& r2, uint32_t& r3,
                                      uint32_t addr) {
    asm volatile("ldmatrix.sync.aligned.m8n8.x4.shared.b16 {%0,%1,%2,%3}, [%4];"
                 : "=r"(r0), "=r"(r1), "=r"(r2), "=r"(r3) : "r"(addr));
}

// write split planes of a float pair into interleaved layout
__device__ __forceinline__ void store3(ushort_t* cat, size_t rowIdx, int nch, int d,
                                       float c0, float c1) {
    uint32_t r0, r1, r2;
    splitpack(c0, c1, r0, r1, r2);
    uint32_t* pb = (uint32_t*)cat;
    const int kc = d >> 4, wi = (d & 15) >> 1;
    const size_t base = (rowIdx * nch + kc) * 3;
    pb[(base + 0) * 8 + wi] = r0;
    pb[(base + 1) * 8 + wi] = r1;
    pb[(base + 2) * 8 + wi] = r2;
}

// ---------------------------------------------------------------------------
// Prep: x -> g_x3, [Wq;Wkv] -> g_w3 (one thread = one float2)
// ---------------------------------------------------------------------------
__global__ __launch_bounds__(256) void prep_kernel(
    const float* __restrict__ x, const float* __restrict__ Wq, const float* __restrict__ Wkv)
{
    const int PX = 4096 * 512;
    const int PW = 3072 * 512;
    int idx = blockIdx.x * 256 + threadIdx.x;
    if (idx >= PX + PW) return;

    if (idx < PX) {
        int m = idx >> 9, kp = idx & 511;
        float2 v = *(const float2*)(x + (size_t)m * 1024 + kp * 2);
        store3(g_x3, (size_t)m, 64, kp * 2, v.x, v.y);
    } else {
        int j = idx - PX;
        int n = j >> 9, kp = j & 511;
        const float* src = (n < 1024) ? (Wq + (size_t)n * 1024)
                                      : (Wkv + (size_t)(n - 1024) * 1024);
        float2 v = *(const float2*)(src + kp * 2);
        store3(g_w3, (size_t)n, 64, kp * 2, v.x, v.y);
    }
}

// ---------------------------------------------------------------------------
// shared GEMM bits
// ---------------------------------------------------------------------------
#define SROW  24
#define SPL   (128 * SROW)         // 3072 shorts per plane
#define NSTG  3
#define SOP   (NSTG * 3 * SPL)     // per operand: 27648 shorts
#define SMEMB (2 * SOP * 2)        // 110592 bytes
#define STG_STRIDE_B (3 * SPL * 2) // 18432 bytes per stage

struct Frag { float acc[2][8][4]; };

// term t -> (A plane, B plane): a0b0, a0b1, a1b0, a1b1, a0b2, a2b0.
// NT=6: full split-3 (bit-exact path, q/k/scores).
// NT=3: keeps the first 3 terms (error ~3*2^-18, used for v only).
#define DO_TERMS_N(ACCSEL, NT)                                               \
    {                                                                        \
        constexpr int TA[6] = {0, 0, 1, 1, 0, 2};                            \
        constexpr int TB[6] = {0, 1, 0, 1, 2, 0};                            \
        _Pragma("unroll")                                                    \
        for (int t = 0; t < (NT); t++) {                                     \
            const int ap = TA[t], bp = TB[t];                                \
            _Pragma("unroll")                                                \
            for (int q = 0; q < 2; q++)                                      \
                _Pragma("unroll")                                            \
                for (int sub = 0; sub < 2; sub++)                            \
                    _Pragma("unroll")                                        \
                    for (int mt = 0; mt < 2; mt++)                           \
                        mma16(F.acc[mt][ACCSEL],                             \
                              Af[mt][ap], Bm[q][bp][sub], Bm[q][bp][sub+2]); \
        }                                                                    \
    }

// R12 load mapping (coalesced: threads t..t+5 cover one contiguous 96B row-chunk)
__device__ __forceinline__ void ld_stage(
    ushort_t* sm, int stage,
    const ushort_t* __restrict__ A, int lda,
    const ushort_t* __restrict__ B, int ldb, int kt)
{
#pragma unroll
    for (int t = threadIdx.x; t < 1536; t += 256) {
        const int side = (t >= 768) ? 1 : 0;
        const int r    = side ? (t - 768) : t;
        const int row  = r / 6;
        const int seg  = r - row * 6;
        const int p    = seg >> 1;
        const int half = seg & 1;
        const ushort_t* src = (side ? B + (size_t)row * ldb
                                    : A + (size_t)row * lda) + kt * 48 + seg * 8;
        uint32_t dst = s2u(&sm[side * SOP + ((stage * 3 + p) * 128 + row) * SROW + half * 8]);
        cp16cg(dst, src);
    }
}

template<int NTERMS>
__device__ __forceinline__ void gemm_planes(
    ushort_t* sm,
    const ushort_t* __restrict__ A, int lda,
    const ushort_t* __restrict__ B, int ldb,
    int NK, Frag& F)
{
    const int tid  = threadIdx.x;
    const int lane = tid & 31;
    const int wid  = tid >> 5;
    const int wm   = wid & 3;
    const int wn   = wid >> 2;

    const int lrow = (lane & 7) + ((lane >> 3) & 1) * 8;
    const int lhal = lane >> 4;

    const uint32_t smb = s2u(sm);
    uint32_t aoff[2], boff[4];
#pragma unroll
    for (int mt = 0; mt < 2; mt++)
        aoff[mt] = smb + ((wm * 32 + mt * 16 + lrow) * SROW + lhal * 8) * 2;
#pragma unroll
    for (int ntp = 0; ntp < 4; ntp++)
        boff[ntp] = smb + SOP * 2 + ((wn * 64 + ntp * 16 + lrow) * SROW + lhal * 8) * 2;

#pragma unroll
    for (int mt = 0; mt < 2; mt++)
#pragma unroll
        for (int nt = 0; nt < 8; nt++)
#pragma unroll
            for (int r = 0; r < 4; r++) F.acc[mt][nt][r] = 0.f;

#pragma unroll
    for (int p = 0; p < NSTG - 1; p++) {
        ld_stage(sm, p, A, lda, B, ldb, p);
        CP_COMMIT();
    }

    for (int kt = 0; kt < NK; kt++) {
        const bool more = (kt + NSTG - 1 < NK);
        if (more) { CP_WAIT(1); } else { CP_WAIT(0); }
        __syncthreads();
        if (more) {
            ld_stage(sm, (kt + NSTG - 1) % NSTG, A, lda, B, ldb, kt + NSTG - 1);
            CP_COMMIT();
        }

        const int buf = kt % 3;
        const uint32_t pbase = (uint32_t)(buf * 3) * SPL * 2;

        uint32_t Af[2][3][4];
#pragma unroll
        for (int mt = 0; mt < 2; mt++)
#pragma unroll
            for (int p = 0; p < 3; p++)
                ldsm4(Af[mt][p][0], Af[mt][p][1], Af[mt][p][2], Af[mt][p][3],
                      aoff[mt] + pbase + p * SPL * 2);

#pragma unroll
        for (int hp = 0; hp < 2; hp++) {
            uint32_t Bm[2][3][4];
#pragma unroll
            for (int q = 0; q < 2; q++)
#pragma unroll
                for (int p = 0; p < 3; p++)
                    ldsm4(Bm[q][p][0], Bm[q][p][1], Bm[q][p][2], Bm[q][p][3],
                          boff[hp * 2 + q] + pbase + p * SPL * 2);
            DO_TERMS_N((hp * 2 + q) * 2 + sub, NTERMS)
        }
    }
    __syncthreads();
}

// ---------------------------------------------------------------------------
// Kernel 1: proj  Y[4096,3072] = x @ [Wq;Wkv]^T
// q/k tiles: 6 terms (bit-exact, feeds argmax). v tiles: 3 terms (~1e-5 err,
// values only — no argmax involvement).
// ---------------------------------------------------------------------------
__global__ __launch_bounds__(256, 2) void proj_tc()
{
    extern __shared__ __align__(16) ushort_t smp[];

    const int m0 = blockIdx.y * 128;
    const int n0 = blockIdx.x * 128;
    const bool isv = (n0 >= 2048);

    Frag F;
    if (isv)
        gemm_planes<3>(smp, g_x3 + (size_t)m0 * 3072, 3072,
                       g_w3 + (size_t)n0 * 3072, 3072, 64, F);
    else
        gemm_planes<6>(smp, g_x3 + (size_t)m0 * 3072, 3072,
                       g_w3 + (size_t)n0 * 3072, 3072, 64, F);

    const int lane = threadIdx.x & 31;
    const int wid  = threadIdx.x >> 5;
    const int wm = wid & 3, wn = wid >> 2;

#pragma unroll
    for (int mt = 0; mt < 2; mt++)
#pragma unroll
        for (int nt = 0; nt < 8; nt++) {
            const int r  = m0 + wm * 32 + mt * 16 + (lane >> 2);
            const int cc = n0 + wn * 64 + nt * 8 + (lane & 3) * 2;
            const float* c = F.acc[mt][nt];
            if (isv) {
                *(float2*)(g_v + (size_t)r * 1024 + (cc - 2048)) = make_float2(c[0], c[1]);
                *(float2*)(g_v + (size_t)(r + 8) * 1024 + (cc - 2048)) = make_float2(c[2], c[3]);
            } else {
                const bool isq = (n0 < 1024);
                const int nn = isq ? cc : cc - 1024;
                const int h = nn >> 6, d = nn & 63;
                const int bidx = r >> 10;
                ushort_t* cat = isq ? g_q3 : g_k3;
                const size_t row0 = (size_t)(bidx * 16 + h) * 1024 + (r & 1023);
                const size_t row1 = (size_t)(bidx * 16 + h) * 1024 + ((r + 8) & 1023);
                store3(cat, row0, 4, d, c[0], c[1]);
                store3(cat, row1, 4, d, c[2], c[3]);
            }
        }
}

// ---------------------------------------------------------------------------
// Kernel 2: score  S[b,h] = (q_h k_h^T)/32
// 4 j-tiles per CTA: A (q tile, all 4 chunks) resident in smem, B (k) streams
// through a 2-stage double buffer. Per output tile: same 4-chunk, same MMA
// order as R4..R12 (bit-exact). [R12 verbatim]
// ---------------------------------------------------------------------------
__device__ __forceinline__ void ld_Bstage(
    ushort_t* smB, int stage, const ushort_t* __restrict__ B, int kt)
{
#pragma unroll
    for (int t = threadIdx.x; t < 768; t += 256) {
        const int row  = t / 6;
        const int seg  = t - row * 6;
        const int p    = seg >> 1;
        const int half = seg & 1;
        cp16cg(s2u(&smB[((stage * 3 + p) * 128 + row) * SROW + half * 8]),
               B + (size_t)row * 192 + kt * 48 + seg * 8);
    }
}

__global__ __launch_bounds__(256, 2) void score_tc()
{
    extern __shared__ __align__(16) ushort_t smp[];
    ushort_t* smA = smp;                 // [4 chunks][3 planes][128][SROW]
    ushort_t* smB = smp + 12 * SPL;      // [2 stages][3 planes][128][SROW]

    const int jt0 = blockIdx.x * 4;
    const int it  = blockIdx.y;
    const int z   = blockIdx.z;

    const ushort_t* Ab = g_q3 + ((size_t)z * 1024 + it * 128) * 192;
    const ushort_t* Bz = g_k3 + (size_t)z * 1024 * 192;

    // prologue: A all 4 chunks + B stage for s=0 (one cp.async group)
    for (int t = threadIdx.x; t < 3072; t += 256) {
        const int c    = t / 768;
        const int rr   = t - c * 768;
        const int row  = rr / 6;
        const int seg  = rr - row * 6;
        const int p    = seg >> 1;
        const int half = seg & 1;
        cp16cg(s2u(&smA[((c * 3 + p) * 128 + row) * SROW + half * 8]),
               Ab + (size_t)row * 192 + c * 48 + seg * 8);
    }
    ld_Bstage(smB, 0, Bz + (size_t)(jt0 * 128) * 192, 0);
    CP_COMMIT();

    const int tid  = threadIdx.x;
    const int lane = tid & 31;
    const int wid  = tid >> 5;
    const int wm   = wid & 3;
    const int wn   = wid >> 2;
    const int lrow = (lane & 7) + ((lane >> 3) & 1) * 8;
    const int lhal = lane >> 4;

    uint32_t aoff[2], boff[4];
#pragma unroll
    for (int mt = 0; mt < 2; mt++)
        aoff[mt] = s2u(smA) + ((wm * 32 + mt * 16 + lrow) * SROW + lhal * 8) * 2;
#pragma unroll
    for (int ntp = 0; ntp < 4; ntp++)
        boff[ntp] = s2u(smB) + ((wn * 64 + ntp * 16 + lrow) * SROW + lhal * 8) * 2;

    Frag F;
#pragma unroll
    for (int mt = 0; mt < 2; mt++)
#pragma unroll
        for (int nt = 0; nt < 8; nt++)
#pragma unroll
            for (int r = 0; r < 4; r++) F.acc[mt][nt][r] = 0.f;

    const float scale = 0.03125f;

    for (int s = 0; s < 16; s++) {
        CP_WAIT(0);
        __syncthreads();
        if (s + 1 < 16) {
            const int jtn = jt0 + (s + 1) / 4;
            const int ktn = (s + 1) & 3;
            ld_Bstage(smB, (s + 1) & 1, Bz + (size_t)(jtn * 128) * 192, ktn);
            CP_COMMIT();
        }

        const int kt = s & 3;
        const uint32_t abase = (uint32_t)(kt * 3) * SPL * 2;
        const uint32_t bbase = (uint32_t)((s & 1) * 3) * SPL * 2;

        uint32_t Af[2][3][4];
#pragma unroll
        for (int mt = 0; mt < 2; mt++)
#pragma unroll
            for (int p = 0; p < 3; p++)
                ldsm4(Af[mt][p][0], Af[mt][p][1], Af[mt][p][2], Af[mt][p][3],
                      aoff[mt] + abase + p * SPL * 2);

#pragma unroll
        for (int hp = 0; hp < 2; hp++) {
            uint32_t Bm[2][3][4];
#pragma unroll
            for (int q = 0; q < 2; q++)
#pragma unroll
                for (int p = 0; p < 3; p++)
                    ldsm4(Bm[q][p][0], Bm[q][p][1], Bm[q][p][2], Bm[q][p][3],
                          boff[hp * 2 + q] + bbase + p * SPL * 2);
            DO_TERMS_N((hp * 2 + q) * 2 + sub, 6)
        }

        if (kt == 3) {
            const int jt = jt0 + (s >> 2);
#pragma unroll
            for (int mt = 0; mt < 2; mt++)
#pragma unroll
                for (int nt = 0; nt < 8; nt++) {
                    int r  = it * 128 + wm * 32 + mt * 16 + (lane >> 2);
                    int cc = jt * 128 + wn * 64 + nt * 8 + (lane & 3) * 2;
                    float* base = g_s + ((size_t)z * Nn + r) * Nn + cc;
                    float* c = F.acc[mt][nt];
                    __stcs((float2*)base, make_float2(c[0] * scale, c[1] * scale));
                    __stcs((float2*)(base + 8 * Nn), make_float2(c[2] * scale, c[3] * scale));
                    c[0] = 0.f; c[1] = 0.f; c[2] = 0.f; c[3] = 0.f;
                }
        }
    }
}

// ---------------------------------------------------------------------------
// Kernel 3: attn — R12 version (unchanged).
// ---------------------------------------------------------------------------
__global__ __launch_bounds__(512) void attn_kernel(
    const float* __restrict__ Wt,
    const float* __restrict__ ln_g,
    const float* __restrict__ ln_b,
    float* __restrict__ out)
{
    extern __shared__ float sm[];
    float* sw   = sm;                 // [16][1024] raw exp values
    float* swt  = sm + Hn * Nn;       // [256]
    float* sg   = swt + 256;          // [16]
    float* sb   = sg + 16;            // [16]
    float* ssum = sb + 16;            // [16]

    const int tid = threadIdx.x;
    const int i   = blockIdx.x;
    const int b   = blockIdx.y;

#pragma unroll
    for (int f = tid; f < Hn * Nn / 4; f += 512) {
        int h = f >> 8;
        int j4 = (f & 255) * 4;
        cp16cg(s2u(sw + h * Nn + j4),
               g_s + ((size_t)(b * Hn + h) * Nn + i) * Nn + j4);
    }
    CP_COMMIT();
    if (tid < 256) swt[tid] = Wt[tid];
    if (tid < 16) { sg[tid] = ln_g[tid]; sb[tid] = ln_b[tid]; }
    CP_WAIT(0);
    __syncthreads();

    const int warp = tid >> 5;
    const int lane = tid & 31;

    {
        float* row = sw + warp * Nn;
        float m = -INFINITY;
        for (int j = lane; j < Nn; j += 32) m = fmaxf(m, row[j]);
#pragma unroll
        for (int o = 16; o; o >>= 1) m = fmaxf(m, __shfl_xor_sync(~0u, m, o));
        float s = 0.f;
        for (int j = lane; j < Nn; j += 32) { float e = expf(row[j] - m); row[j] = e; s += e; }
#pragma unroll
        for (int o = 16; o; o >>= 1) s += __shfl_xor_sync(~0u, s, o);
        if (lane == 0) ssum[warp] = s;
    }
    __syncthreads();

    for (int j = tid; j < Nn; j += 512) {
        float wc[16];
#pragma unroll
        for (int h = 0; h < 16; h++) wc[h] = sw[h * Nn + j] / ssum[h];
        float mix[16];
        float mu = 0.f;
#pragma unroll
        for (int ho = 0; ho < 16; ho++) {
            float acc = 0.f;
#pragma unroll
            for (int h = 0; h < 16; h++) acc += swt[ho * 16 + h] * wc[h];
            mix[ho] = acc;
            mu += acc;
        }
        mu *= (1.f / 16.f);
        float var = 0.f;
#pragma unroll
        for (int ho = 0; ho < 16; ho++) { float d = mix[ho] - mu; var += d * d; }
        var *= (1.f / 16.f);
        const float denom = sqrtf(var + 1e-5f);
#pragma unroll
        for (int ho = 0; ho < 16; ho++)
            sw[ho * Nn + j] = (mix[ho] - mu) / denom * sg[ho] + sb[ho];
    }
    __syncthreads();

    {
        const int h = warp;
        float* row = sw + h * Nn;
        float bv = -INFINITY;
        int   bi = 0;
        for (int j = lane; j < Nn; j += 32) {
            float v = row[j];
            if (v > bv) { bv = v; bi = j; }
        }
#pragma unroll
        for (int o = 16; o; o >>= 1) {
            float ov = __shfl_xor_sync(~0u, bv, o);
            int   oi = __shfl_xor_sync(~0u, bi, o);
            if (ov > bv || (ov == bv && oi < bi)) { bv = ov; bi = oi; }
        }
        const float* vsrc = g_v + (size_t)(b * Nn + bi) * 1024 + h * DHn;
        float* dst = out + (size_t)(b * Nn + i) * Dn + h * DHn;
#pragma unroll
        for (int d = lane; d < DHn; d += 32) dst[d] = vsrc[d];
    }
}

// ---------------------------------------------------------------------------
extern "C" void kernel_launch(void* const* d_in, const int* in_sizes, int n_in,
                              void* d_out, int out_size)
{
    const float* x    = (const float*)d_in[0];
    const float* Wq   = (const float*)d_in[1];
    const float* Wkv  = (const float*)d_in[2];
    const float* Wt   = (const float*)d_in[3];
    const float* ln_g = (const float*)d_in[4];
    const float* ln_b = (const float*)d_in[5];
    float* out = (float*)d_out;

    const int total = (4096 + 3072) * 512;
    prep_kernel<<<(total + 255) / 256, 256>>>(x, Wq, Wkv);

    cudaFuncSetAttribute(proj_tc, cudaFuncAttributeMaxDynamicSharedMemorySize, SMEMB);
    cudaFuncSetAttribute(score_tc, cudaFuncAttributeMaxDynamicSharedMemorySize, SMEMB);

    proj_tc<<<dim3(3072 / 128, 4096 / 128), 256, SMEMB>>>();
    score_tc<<<dim3(Nn / 512, Nn / 128, Bn * Hn), 256, SMEMB>>>();

    const int asmem = (Hn * Nn + 256 + 16 + 16 + 16) * sizeof(float);
    cudaFuncSetAttribute(attn_kernel, cudaFuncAttributeMaxDynamicSharedMemorySize, asmem);
    attn_kernel<<<dim3(Nn, Bn), 512, asmem>>>(Wt, ln_g, ln_b, out);
}

// round 16
// speedup vs baseline: 1.2381x; 1.0044x over previous
#include <cuda_runtime.h>
#include <math.h>
#include <cstdint>

#define Bn   4
#define Nn   1024
#define Dn   1024
#define Hn   16
#define DHn  64

typedef unsigned short ushort_t;

// ---------------------------------------------------------------------------
// Scratch (__device__ globals)
// Interleaved split-plane layout per operand: [row][kchunk][plane(3)][16] bf16
// ---------------------------------------------------------------------------
__device__ __align__(16) ushort_t g_x3[(size_t)4096 * 64 * 48];     // 25.2 MB
__device__ __align__(16) ushort_t g_w3[(size_t)3072 * 64 * 48];     // 18.9 MB
__device__ __align__(16) ushort_t g_q3[(size_t)64 * 1024 * 4 * 48]; // 25.2 MB
__device__ __align__(16) ushort_t g_k3[(size_t)64 * 1024 * 4 * 48]; // 25.2 MB
__device__ float g_v[(size_t)4096 * 1024];                          // 16.8 MB
__device__ float g_s[(size_t)64 * 1024 * 1024];                     // 268.4 MB

// ---------------------------------------------------------------------------
// helpers
// ---------------------------------------------------------------------------
__device__ __forceinline__ uint32_t s2u(const void* p) {
    uint32_t a;
    asm("{ .reg .u64 t; cvta.to.shared.u64 t, %1; cvt.u32.u64 %0, t; }" : "=r"(a) : "l"(p));
    return a;
}
__device__ __forceinline__ void cp16cg(uint32_t s, const void* g) {
    asm volatile("cp.async.cg.shared.global [%0], [%1], 16;" :: "r"(s), "l"(g));
}
#define CP_COMMIT() asm volatile("cp.async.commit_group;" ::: "memory")
#define CP_WAIT(n)  asm volatile("cp.async.wait_group %0;" :: "n"(n) : "memory")

// 3-way bf16 split: f = b0 + b1 + b2  (deterministic; identical to R4..R15)
__device__ __forceinline__ void split3(float f, ushort_t& u0, ushort_t& u1, ushort_t& u2) {
    ushort_t h0;
    asm("cvt.rn.bf16.f32 %0, %1;" : "=h"(h0) : "f"(f));
    float f0; asm("cvt.f32.bf16 %0, %1;" : "=f"(f0) : "h"(h0));
    float r1 = f - f0;
    ushort_t h1;
    asm("cvt.rn.bf16.f32 %0, %1;" : "=h"(h1) : "f"(r1));
    float f1; asm("cvt.f32.bf16 %0, %1;" : "=f"(f1) : "h"(h1));
    float r2 = r1 - f1;
    ushort_t h2;
    asm("cvt.rn.bf16.f32 %0, %1;" : "=h"(h2) : "f"(r2));
    u0 = h0; u1 = h1; u2 = h2;
}
__device__ __forceinline__ void splitpack(float fx, float fy,
                                          uint32_t& r0, uint32_t& r1, uint32_t& r2) {
    ushort_t a0, a1, a2, b0, b1, b2;
    split3(fx, a0, a1, a2);
    split3(fy, b0, b1, b2);
    r0 = (uint32_t)a0 | ((uint32_t)b0 << 16);
    r1 = (uint32_t)a1 | ((uint32_t)b1 << 16);
    r2 = (uint32_t)a2 | ((uint32_t)b2 << 16);
}
__device__ __forceinline__ void mma16(float* c, const uint32_t* a, uint32_t b0, uint32_t b1) {
    asm volatile(
        "mma.sync.aligned.m16n8k16.row.col.f32.bf16.bf16.f32 "
        "{%0,%1,%2,%3}, {%4,%5,%6,%7}, {%8,%9}, {%0,%1,%2,%3};"
        : "+f"(c[0]), "+f"(c[1]), "+f"(c[2]), "+f"(c[3])
        : "r"(a[0]), "r"(a[1]), "r"(a[2]), "r"(a[3]), "r"(b0), "r"(b1));
}
__device__ __forceinline__ void ldsm4(uint32_t& r0, uint32_t& r1, uint32_t& r2, uint32_t& r3,
                                      uint32_t addr) {
    asm volatile("ldmatrix.sync.aligned.m8n8.x4.shared.b16 {%0,%1,%2,%3}, [%4];"
                 : "=r"(r0), "=r"(r1), "=r"(r2), "=r"(r3) : "r"(addr));
}

// write split planes of a float pair into interleaved layout
__device__ __forceinline__ void store3(ushort_t* cat, size_t rowIdx, int nch, int d,
                                       float c0, float c1) {
    uint32_t r0, r1, r2;
    splitpack(c0, c1, r0, r1, r2);
    uint32_t* pb = (uint32_t*)cat;
    const int kc = d >> 4, wi = (d & 15) >> 1;
    const size_t base = (rowIdx * nch + kc) * 3;
    pb[(base + 0) * 8 + wi] = r0;
    pb[(base + 1) * 8 + wi] = r1;
    pb[(base + 2) * 8 + wi] = r2;
}

// ---------------------------------------------------------------------------
// Prep: x -> g_x3, [Wq;Wkv] -> g_w3 (one thread = one float2)
// ---------------------------------------------------------------------------
__global__ __launch_bounds__(256) void prep_kernel(
    const float* __restrict__ x, const float* __restrict__ Wq, const float* __restrict__ Wkv)
{
    const int PX = 4096 * 512;
    const int PW = 3072 * 512;
    int idx = blockIdx.x * 256 + threadIdx.x;
    if (idx >= PX + PW) return;

    if (idx < PX) {
        int m = idx >> 9, kp = idx & 511;
        float2 v = *(const float2*)(x + (size_t)m * 1024 + kp * 2);
        store3(g_x3, (size_t)m, 64, kp * 2, v.x, v.y);
    } else {
        int j = idx - PX;
        int n = j >> 9, kp = j & 511;
        const float* src = (n < 1024) ? (Wq + (size_t)n * 1024)
                                      : (Wkv + (size_t)(n - 1024) * 1024);
        float2 v = *(const float2*)(src + kp * 2);
        store3(g_w3, (size_t)n, 64, kp * 2, v.x, v.y);
    }
}

// ---------------------------------------------------------------------------
// shared GEMM bits
// ---------------------------------------------------------------------------
#define SROW  24
#define SPL   (128 * SROW)         // 3072 shorts per plane
#define NSTG  3
#define SOP   (NSTG * 3 * SPL)     // per operand: 27648 shorts
#define SMEMB (2 * SOP * 2)        // 110592 bytes
#define STG_STRIDE_B (3 * SPL * 2) // 18432 bytes per stage

struct Frag { float acc[2][8][4]; };

// term t -> (A plane, B plane): a0b0, a0b1, a1b0, a1b1, a0b2, a2b0.
// NT=6: full split-3 (bit-exact path, q/k/scores).
// NT=3: keeps the first 3 terms (error ~3*2^-18, used for v only).
#define DO_TERMS_N(ACCSEL, NT)                                               \
    {                                                                        \
        constexpr int TA[6] = {0, 0, 1, 1, 0, 2};                            \
        constexpr int TB[6] = {0, 1, 0, 1, 2, 0};                            \
        _Pragma("unroll")                                                    \
        for (int t = 0; t < (NT); t++) {                                     \
            const int ap = TA[t], bp = TB[t];                                \
            _Pragma("unroll")                                                \
            for (int q = 0; q < 2; q++)                                      \
                _Pragma("unroll")                                            \
                for (int sub = 0; sub < 2; sub++)                            \
                    _Pragma("unroll")                                        \
                    for (int mt = 0; mt < 2; mt++)                           \
                        mma16(F.acc[mt][ACCSEL],                             \
                              Af[mt][ap], Bm[q][bp][sub], Bm[q][bp][sub+2]); \
        }                                                                    \
    }

// Stage loader, templated on plane count.
// NPL=3 (R12 mapping): threads t..t+5 cover one contiguous 96B row-chunk.
// NPL=2: threads t..t+3 cover the first 64B (planes 0,1) of a row-chunk.
template<int NPL>
__device__ __forceinline__ void ld_stage(
    ushort_t* sm, int stage,
    const ushort_t* __restrict__ A, int lda,
    const ushort_t* __restrict__ B, int ldb, int kt)
{
    constexpr int SEGS  = 2 * NPL;            // 16B segments per row-chunk
    constexpr int TOT   = 2 * 128 * SEGS;     // both operands
#pragma unroll
    for (int t = threadIdx.x; t < TOT; t += 256) {
        const int side = (t >= TOT / 2) ? 1 : 0;
        const int r    = side ? (t - TOT / 2) : t;
        const int row  = r / SEGS;
        const int seg  = r - row * SEGS;
        const int p    = seg >> 1;
        const int half = seg & 1;
        const ushort_t* src = (side ? B + (size_t)row * ldb
                                    : A + (size_t)row * lda) + kt * 48 + seg * 8;
        uint32_t dst = s2u(&sm[side * SOP + ((stage * 3 + p) * 128 + row) * SROW + half * 8]);
        cp16cg(dst, src);
    }
}

template<int NTERMS>
__device__ __forceinline__ void gemm_planes(
    ushort_t* sm,
    const ushort_t* __restrict__ A, int lda,
    const ushort_t* __restrict__ B, int ldb,
    int NK, Frag& F)
{
    constexpr int NPL = (NTERMS > 3) ? 3 : 2;   // planes actually used by terms

    const int tid  = threadIdx.x;
    const int lane = tid & 31;
    const int wid  = tid >> 5;
    const int wm   = wid & 3;
    const int wn   = wid >> 2;

    const int lrow = (lane & 7) + ((lane >> 3) & 1) * 8;
    const int lhal = lane >> 4;

    const uint32_t smb = s2u(sm);
    uint32_t aoff[2], boff[4];
#pragma unroll
    for (int mt = 0; mt < 2; mt++)
        aoff[mt] = smb + ((wm * 32 + mt * 16 + lrow) * SROW + lhal * 8) * 2;
#pragma unroll
    for (int ntp = 0; ntp < 4; ntp++)
        boff[ntp] = smb + SOP * 2 + ((wn * 64 + ntp * 16 + lrow) * SROW + lhal * 8) * 2;

#pragma unroll
    for (int mt = 0; mt < 2; mt++)
#pragma unroll
        for (int nt = 0; nt < 8; nt++)
#pragma unroll
            for (int r = 0; r < 4; r++) F.acc[mt][nt][r] = 0.f;

#pragma unroll
    for (int p = 0; p < NSTG - 1; p++) {
        ld_stage<NPL>(sm, p, A, lda, B, ldb, p);
        CP_COMMIT();
    }

    for (int kt = 0; kt < NK; kt++) {
        const bool more = (kt + NSTG - 1 < NK);
        if (more) { CP_WAIT(1); } else { CP_WAIT(0); }
        __syncthreads();
        if (more) {
            ld_stage<NPL>(sm, (kt + NSTG - 1) % NSTG, A, lda, B, ldb, kt + NSTG - 1);
            CP_COMMIT();
        }

        const int buf = kt % 3;
        const uint32_t pbase = (uint32_t)(buf * 3) * SPL * 2;

        uint32_t Af[2][3][4];
#pragma unroll
        for (int mt = 0; mt < 2; mt++)
#pragma unroll
            for (int p = 0; p < NPL; p++)
                ldsm4(Af[mt][p][0], Af[mt][p][1], Af[mt][p][2], Af[mt][p][3],
                      aoff[mt] + pbase + p * SPL * 2);

#pragma unroll
        for (int hp = 0; hp < 2; hp++) {
            uint32_t Bm[2][3][4];
#pragma unroll
            for (int q = 0; q < 2; q++)
#pragma unroll
                for (int p = 0; p < NPL; p++)
                    ldsm4(Bm[q][p][0], Bm[q][p][1], Bm[q][p][2], Bm[q][p][3],
                          boff[hp * 2 + q] + pbase + p * SPL * 2);
            DO_TERMS_N((hp * 2 + q) * 2 + sub, NTERMS)
        }
    }
    __syncthreads();
}

// ---------------------------------------------------------------------------
// Kernel 1: proj  Y[4096,3072] = x @ [Wq;Wkv]^T
// q/k tiles: 6 terms / 3 planes (bit-exact, feeds argmax).
// v tiles: 3 terms / 2 planes (values only; plane 2 never touched).
// ---------------------------------------------------------------------------
__global__ __launch_bounds__(256, 2) void proj_tc()
{
    extern __shared__ __align__(16) ushort_t smp[];

    const int m0 = blockIdx.y * 128;
    const int n0 = blockIdx.x * 128;
    const bool isv = (n0 >= 2048);

    Frag F;
    if (isv)
        gemm_planes<3>(smp, g_x3 + (size_t)m0 * 3072, 3072,
                       g_w3 + (size_t)n0 * 3072, 3072, 64, F);
    else
        gemm_planes<6>(smp, g_x3 + (size_t)m0 * 3072, 3072,
                       g_w3 + (size_t)n0 * 3072, 3072, 64, F);

    const int lane = threadIdx.x & 31;
    const int wid  = threadIdx.x >> 5;
    const int wm = wid & 3, wn = wid >> 2;

#pragma unroll
    for (int mt = 0; mt < 2; mt++)
#pragma unroll
        for (int nt = 0; nt < 8; nt++) {
            const int r  = m0 + wm * 32 + mt * 16 + (lane >> 2);
            const int cc = n0 + wn * 64 + nt * 8 + (lane & 3) * 2;
            const float* c = F.acc[mt][nt];
            if (isv) {
                *(float2*)(g_v + (size_t)r * 1024 + (cc - 2048)) = make_float2(c[0], c[1]);
                *(float2*)(g_v + (size_t)(r + 8) * 1024 + (cc - 2048)) = make_float2(c[2], c[3]);
            } else {
                const bool isq = (n0 < 1024);
                const int nn = isq ? cc : cc - 1024;
                const int h = nn >> 6, d = nn & 63;
                const int bidx = r >> 10;
                ushort_t* cat = isq ? g_q3 : g_k3;
                const size_t row0 = (size_t)(bidx * 16 + h) * 1024 + (r & 1023);
                const size_t row1 = (size_t)(bidx * 16 + h) * 1024 + ((r + 8) & 1023);
                store3(cat, row0, 4, d, c[0], c[1]);
                store3(cat, row1, 4, d, c[2], c[3]);
            }
        }
}

// ---------------------------------------------------------------------------
// Kernel 2: score  S[b,h] = (q_h k_h^T)/32
// 4 j-tiles per CTA: A (q tile, all 4 chunks) resident in smem, B (k) streams
// through a 2-stage double buffer. Per output tile: same 4-chunk, same MMA
// order as R4..R15 (bit-exact). [R12 verbatim]
// ---------------------------------------------------------------------------
__device__ __forceinline__ void ld_Bstage(
    ushort_t* smB, int stage, const ushort_t* __restrict__ B, int kt)
{
#pragma unroll
    for (int t = threadIdx.x; t < 768; t += 256) {
        const int row  = t / 6;
        const int seg  = t - row * 6;
        const int p    = seg >> 1;
        const int half = seg & 1;
        cp16cg(s2u(&smB[((stage * 3 + p) * 128 + row) * SROW + half * 8]),
               B + (size_t)row * 192 + kt * 48 + seg * 8);
    }
}

__global__ __launch_bounds__(256, 2) void score_tc()
{
    extern __shared__ __align__(16) ushort_t smp[];
    ushort_t* smA = smp;                 // [4 chunks][3 planes][128][SROW]
    ushort_t* smB = smp + 12 * SPL;      // [2 stages][3 planes][128][SROW]

    const int jt0 = blockIdx.x * 4;
    const int it  = blockIdx.y;
    const int z   = blockIdx.z;

    const ushort_t* Ab = g_q3 + ((size_t)z * 1024 + it * 128) * 192;
    const ushort_t* Bz = g_k3 + (size_t)z * 1024 * 192;

    // prologue: A all 4 chunks + B stage for s=0 (one cp.async group)
    for (int t = threadIdx.x; t < 3072; t += 256) {
        const int c    = t / 768;
        const int rr   = t - c * 768;
        const int row  = rr / 6;
        const int seg  = rr - row * 6;
        const int p    = seg >> 1;
        const int half = seg & 1;
        cp16cg(s2u(&smA[((c * 3 + p) * 128 + row) * SROW + half * 8]),
               Ab + (size_t)row * 192 + c * 48 + seg * 8);
    }
    ld_Bstage(smB, 0, Bz + (size_t)(jt0 * 128) * 192, 0);
    CP_COMMIT();

    const int tid  = threadIdx.x;
    const int lane = tid & 31;
    const int wid  = tid >> 5;
    const int wm   = wid & 3;
    const int wn   = wid >> 2;
    const int lrow = (lane & 7) + ((lane >> 3) & 1) * 8;
    const int lhal = lane >> 4;

    uint32_t aoff[2], boff[4];
#pragma unroll
    for (int mt = 0; mt < 2; mt++)
        aoff[mt] = s2u(smA) + ((wm * 32 + mt * 16 + lrow) * SROW + lhal * 8) * 2;
#pragma unroll
    for (int ntp = 0; ntp < 4; ntp++)
        boff[ntp] = s2u(smB) + ((wn * 64 + ntp * 16 + lrow) * SROW + lhal * 8) * 2;

    Frag F;
#pragma unroll
    for (int mt = 0; mt < 2; mt++)
#pragma unroll
        for (int nt = 0; nt < 8; nt++)
#pragma unroll
            for (int r = 0; r < 4; r++) F.acc[mt][nt][r] = 0.f;

    const float scale = 0.03125f;

    for (int s = 0; s < 16; s++) {
        CP_WAIT(0);
        __syncthreads();
        if (s + 1 < 16) {
            const int jtn = jt0 + (s + 1) / 4;
            const int ktn = (s + 1) & 3;
            ld_Bstage(smB, (s + 1) & 1, Bz + (size_t)(jtn * 128) * 192, ktn);
            CP_COMMIT();
        }

        const int kt = s & 3;
        const uint32_t abase = (uint32_t)(kt * 3) * SPL * 2;
        const uint32_t bbase = (uint32_t)((s & 1) * 3) * SPL * 2;

        uint32_t Af[2][3][4];
#pragma unroll
        for (int mt = 0; mt < 2; mt++)
#pragma unroll
            for (int p = 0; p < 3; p++)
                ldsm4(Af[mt][p][0], Af[mt][p][1], Af[mt][p][2], Af[mt][p][3],
                      aoff[mt] + abase + p * SPL * 2);

#pragma unroll
        for (int hp = 0; hp < 2; hp++) {
            uint32_t Bm[2][3][4];
#pragma unroll
            for (int q = 0; q < 2; q++)
#pragma unroll
                for (int p = 0; p < 3; p++)
                    ldsm4(Bm[q][p][0], Bm[q][p][1], Bm[q][p][2], Bm[q][p][3],
                          boff[hp * 2 + q] + bbase + p * SPL * 2);
            DO_TERMS_N((hp * 2 + q) * 2 + sub, 6)
        }

        if (kt == 3) {
            const int jt = jt0 + (s >> 2);
#pragma unroll
            for (int mt = 0; mt < 2; mt++)
#pragma unroll
                for (int nt = 0; nt < 8; nt++) {
                    int r  = it * 128 + wm * 32 + mt * 16 + (lane >> 2);
                    int cc = jt * 128 + wn * 64 + nt * 8 + (lane & 3) * 2;
                    float* base = g_s + ((size_t)z * Nn + r) * Nn + cc;
                    float* c = F.acc[mt][nt];
                    __stcs((float2*)base, make_float2(c[0] * scale, c[1] * scale));
                    __stcs((float2*)(base + 8 * Nn), make_float2(c[2] * scale, c[3] * scale));
                    c[0] = 0.f; c[1] = 0.f; c[2] = 0.f; c[3] = 0.f;
                }
        }
    }
}

// ---------------------------------------------------------------------------
// Kernel 3: attn — R12 version (unchanged).
// ---------------------------------------------------------------------------
__global__ __launch_bounds__(512) void attn_kernel(
    const float* __restrict__ Wt,
    const float* __restrict__ ln_g,
    const float* __restrict__ ln_b,
    float* __restrict__ out)
{
    extern __shared__ float sm[];
    float* sw   = sm;                 // [16][1024] raw exp values
    float* swt  = sm + Hn * Nn;       // [256]
    float* sg   = swt + 256;          // [16]
    float* sb   = sg + 16;            // [16]
    float* ssum = sb + 16;            // [16]

    const int tid = threadIdx.x;
    const int i   = blockIdx.x;
    const int b   = blockIdx.y;

#pragma unroll
    for (int f = tid; f < Hn * Nn / 4; f += 512) {
        int h = f >> 8;
        int j4 = (f & 255) * 4;
        cp16cg(s2u(sw + h * Nn + j4),
               g_s + ((size_t)(b * Hn + h) * Nn + i) * Nn + j4);
    }
    CP_COMMIT();
    if (tid < 256) swt[tid] = Wt[tid];
    if (tid < 16) { sg[tid] = ln_g[tid]; sb[tid] = ln_b[tid]; }
    CP_WAIT(0);
    __syncthreads();

    const int warp = tid >> 5;
    const int lane = tid & 31;

    {
        float* row = sw + warp * Nn;
        float m = -INFINITY;
        for (int j = lane; j < Nn; j += 32) m = fmaxf(m, row[j]);
#pragma unroll
        for (int o = 16; o; o >>= 1) m = fmaxf(m, __shfl_xor_sync(~0u, m, o));
        float s = 0.f;
        for (int j = lane; j < Nn; j += 32) { float e = expf(row[j] - m); row[j] = e; s += e; }
#pragma unroll
        for (int o = 16; o; o >>= 1) s += __shfl_xor_sync(~0u, s, o);
        if (lane == 0) ssum[warp] = s;
    }
    __syncthreads();

    for (int j = tid; j < Nn; j += 512) {
        float wc[16];
#pragma unroll
        for (int h = 0; h < 16; h++) wc[h] = sw[h * Nn + j] / ssum[h];
        float mix[16];
        float mu = 0.f;
#pragma unroll
        for (int ho = 0; ho < 16; ho++) {
            float acc = 0.f;
#pragma unroll
            for (int h = 0; h < 16; h++) acc += swt[ho * 16 + h] * wc[h];
            mix[ho] = acc;
            mu += acc;
        }
        mu *= (1.f / 16.f);
        float var = 0.f;
#pragma unroll
        for (int ho = 0; ho < 16; ho++) { float d = mix[ho] - mu; var += d * d; }
        var *= (1.f / 16.f);
        const float denom = sqrtf(var + 1e-5f);
#pragma unroll
        for (int ho = 0; ho < 16; ho++)
            sw[ho * Nn + j] = (mix[ho] - mu) / denom * sg[ho] + sb[ho];
    }
    __syncthreads();

    {
        const int h = warp;
        float* row = sw + h * Nn;
        float bv = -INFINITY;
        int   bi = 0;
        for (int j = lane; j < Nn; j += 32) {
            float v = row[j];
            if (v > bv) { bv = v; bi = j; }
        }
#pragma unroll
        for (int o = 16; o; o >>= 1) {
            float ov = __shfl_xor_sync(~0u, bv, o);
            int   oi = __shfl_xor_sync(~0u, bi, o);
            if (ov > bv || (ov == bv && oi < bi)) { bv = ov; bi = oi; }
        }
        const float* vsrc = g_v + (size_t)(b * Nn + bi) * 1024 + h * DHn;
        float* dst = out + (size_t)(b * Nn + i) * Dn + h * DHn;
#pragma unroll
        for (int d = lane; d < DHn; d += 32) dst[d] = vsrc[d];
    }
}

// ---------------------------------------------------------------------------
extern "C" void kernel_launch(void* const* d_in, const int* in_sizes, int n_in,
                              void* d_out, int out_size)
{
    const float* x    = (const float*)d_in[0];
    const float* Wq   = (const float*)d_in[1];
    const float* Wkv  = (const float*)d_in[2];
    const float* Wt   = (const float*)d_in[3];
    const float* ln_g = (const float*)d_in[4];
    const float* ln_b = (const float*)d_in[5];
    float* out = (float*)d_out;

    const int total = (4096 + 3072) * 512;
    prep_kernel<<<(total + 255) / 256, 256>>>(x, Wq, Wkv);

    cudaFuncSetAttribute(proj_tc, cudaFuncAttributeMaxDynamicSharedMemorySize, SMEMB);
    cudaFuncSetAttribute(score_tc, cudaFuncAttributeMaxDynamicSharedMemorySize, SMEMB);

    proj_tc<<<dim3(3072 / 128, 4096 / 128), 256, SMEMB>>>();
    score_tc<<<dim3(Nn / 512, Nn / 128, Bn * Hn), 256, SMEMB>>>();

    const int asmem = (Hn * Nn + 256 + 16 + 16 + 16) * sizeof(float);
    cudaFuncSetAttribute(attn_kernel, cudaFuncAttributeMaxDynamicSharedMemorySize, asmem);
    attn_kernel<<<dim3(Nn, Bn), 512, asmem>>>(Wt, ln_g, ln_b, out);
}

// round 17
// speedup vs baseline: 1.2544x; 1.0132x over previous
#include <cuda_runtime.h>
#include <math.h>
#include <cstdint>

#define Bn   4
#define Nn   1024
#define Dn   1024
#define Hn   16
#define DHn  64

typedef unsigned short ushort_t;

// ---------------------------------------------------------------------------
// Scratch (__device__ globals)
// bf16 split planes (q/k path): [row][kchunk][plane(3)][16] bf16
// fp16 single planes (v path):  [row][kchunk][16] fp16
// ---------------------------------------------------------------------------
__device__ __align__(16) ushort_t g_x3[(size_t)4096 * 64 * 48];     // 25.2 MB
__device__ __align__(16) ushort_t g_w3[(size_t)3072 * 64 * 48];     // 18.9 MB
__device__ __align__(16) ushort_t g_xh[(size_t)4096 * 64 * 16];     //  8.4 MB fp16 x
__device__ __align__(16) ushort_t g_wh[(size_t)1024 * 64 * 16];     //  2.1 MB fp16 Wv
__device__ __align__(16) ushort_t g_q3[(size_t)64 * 1024 * 4 * 48]; // 25.2 MB
__device__ __align__(16) ushort_t g_k3[(size_t)64 * 1024 * 4 * 48]; // 25.2 MB
__device__ float g_v[(size_t)4096 * 1024];                          // 16.8 MB
__device__ float g_s[(size_t)64 * 1024 * 1024];                     // 268.4 MB

// ---------------------------------------------------------------------------
// helpers
// ---------------------------------------------------------------------------
__device__ __forceinline__ uint32_t s2u(const void* p) {
    uint32_t a;
    asm("{ .reg .u64 t; cvta.to.shared.u64 t, %1; cvt.u32.u64 %0, t; }" : "=r"(a) : "l"(p));
    return a;
}
__device__ __forceinline__ void cp16cg(uint32_t s, const void* g) {
    asm volatile("cp.async.cg.shared.global [%0], [%1], 16;" :: "r"(s), "l"(g));
}
#define CP_COMMIT() asm volatile("cp.async.commit_group;" ::: "memory")
#define CP_WAIT(n)  asm volatile("cp.async.wait_group %0;" :: "n"(n) : "memory")

// 3-way bf16 split: f = b0 + b1 + b2  (deterministic; identical to R4..R16)
__device__ __forceinline__ void split3(float f, ushort_t& u0, ushort_t& u1, ushort_t& u2) {
    ushort_t h0;
    asm("cvt.rn.bf16.f32 %0, %1;" : "=h"(h0) : "f"(f));
    float f0; asm("cvt.f32.bf16 %0, %1;" : "=f"(f0) : "h"(h0));
    float r1 = f - f0;
    ushort_t h1;
    asm("cvt.rn.bf16.f32 %0, %1;" : "=h"(h1) : "f"(r1));
    float f1; asm("cvt.f32.bf16 %0, %1;" : "=f"(f1) : "h"(h1));
    float r2 = r1 - f1;
    ushort_t h2;
    asm("cvt.rn.bf16.f32 %0, %1;" : "=h"(h2) : "f"(r2));
    u0 = h0; u1 = h1; u2 = h2;
}
__device__ __forceinline__ void splitpack(float fx, float fy,
                                          uint32_t& r0, uint32_t& r1, uint32_t& r2) {
    ushort_t a0, a1, a2, b0, b1, b2;
    split3(fx, a0, a1, a2);
    split3(fy, b0, b1, b2);
    r0 = (uint32_t)a0 | ((uint32_t)b0 << 16);
    r1 = (uint32_t)a1 | ((uint32_t)b1 << 16);
    r2 = (uint32_t)a2 | ((uint32_t)b2 << 16);
}
__device__ __forceinline__ uint32_t packf16(float fx, float fy) {
    ushort_t hx, hy;
    asm("cvt.rn.f16.f32 %0, %1;" : "=h"(hx) : "f"(fx));
    asm("cvt.rn.f16.f32 %0, %1;" : "=h"(hy) : "f"(fy));
    return (uint32_t)hx | ((uint32_t)hy << 16);
}
__device__ __forceinline__ void mma16(float* c, const uint32_t* a, uint32_t b0, uint32_t b1) {
    asm volatile(
        "mma.sync.aligned.m16n8k16.row.col.f32.bf16.bf16.f32 "
        "{%0,%1,%2,%3}, {%4,%5,%6,%7}, {%8,%9}, {%0,%1,%2,%3};"
        : "+f"(c[0]), "+f"(c[1]), "+f"(c[2]), "+f"(c[3])
        : "r"(a[0]), "r"(a[1]), "r"(a[2]), "r"(a[3]), "r"(b0), "r"(b1));
}
__device__ __forceinline__ void mma16h(float* c, const uint32_t* a, uint32_t b0, uint32_t b1) {
    asm volatile(
        "mma.sync.aligned.m16n8k16.row.col.f32.f16.f16.f32 "
        "{%0,%1,%2,%3}, {%4,%5,%6,%7}, {%8,%9}, {%0,%1,%2,%3};"
        : "+f"(c[0]), "+f"(c[1]), "+f"(c[2]), "+f"(c[3])
        : "r"(a[0]), "r"(a[1]), "r"(a[2]), "r"(a[3]), "r"(b0), "r"(b1));
}
__device__ __forceinline__ void ldsm4(uint32_t& r0, uint32_t& r1, uint32_t& r2, uint32_t& r3,
                                      uint32_t addr) {
    asm volatile("ldmatrix.sync.aligned.m8n8.x4.shared.b16 {%0,%1,%2,%3}, [%4];"
                 : "=r"(r0), "=r"(r1), "=r"(r2), "=r"(r3) : "r"(addr));
}

// write split planes of a float pair into interleaved layout
__device__ __forceinline__ void store3(ushort_t* cat, size_t rowIdx, int nch, int d,
                                       float c0, float c1) {
    uint32_t r0, r1, r2;
    splitpack(c0, c1, r0, r1, r2);
    uint32_t* pb = (uint32_t*)cat;
    const int kc = d >> 4, wi = (d & 15) >> 1;
    const size_t base = (rowIdx * nch + kc) * 3;
    pb[(base + 0) * 8 + wi] = r0;
    pb[(base + 1) * 8 + wi] = r1;
    pb[(base + 2) * 8 + wi] = r2;
}

// ---------------------------------------------------------------------------
// Prep: x -> g_x3 (bf16 planes) + g_xh (fp16); W -> g_w3; Wv also -> g_wh.
// ---------------------------------------------------------------------------
__global__ __launch_bounds__(256) void prep_kernel(
    const float* __restrict__ x, const float* __restrict__ Wq, const float* __restrict__ Wkv)
{
    const int PX = 4096 * 512;
    const int PW = 3072 * 512;
    int idx = blockIdx.x * 256 + threadIdx.x;
    if (idx >= PX + PW) return;

    if (idx < PX) {
        int m = idx >> 9, kp = idx & 511;
        float2 v = *(const float2*)(x + (size_t)m * 1024 + kp * 2);
        store3(g_x3, (size_t)m, 64, kp * 2, v.x, v.y);
        ((uint32_t*)g_xh)[((size_t)m * 64 + (kp >> 3)) * 8 + (kp & 7)] = packf16(v.x, v.y);
    } else {
        int j = idx - PX;
        int n = j >> 9, kp = j & 511;
        const float* src = (n < 1024) ? (Wq + (size_t)n * 1024)
                                      : (Wkv + (size_t)(n - 1024) * 1024);
        float2 v = *(const float2*)(src + kp * 2);
        store3(g_w3, (size_t)n, 64, kp * 2, v.x, v.y);
        if (n >= 2048)
            ((uint32_t*)g_wh)[((size_t)(n - 2048) * 64 + (kp >> 3)) * 8 + (kp & 7)] =
                packf16(v.x, v.y);
    }
}

// ---------------------------------------------------------------------------
// shared GEMM bits
// ---------------------------------------------------------------------------
#define SROW  24
#define SPL   (128 * SROW)         // 3072 shorts per plane
#define NSTG  3
#define SOP   (NSTG * 3 * SPL)     // per operand: 27648 shorts
#define SMEMB (2 * SOP * 2)        // 110592 bytes
#define STG_STRIDE_B (3 * SPL * 2) // 18432 bytes per stage

struct Frag { float acc[2][8][4]; };

// term t -> (A plane, B plane): a0b0, a0b1, a1b0, a1b1, a0b2, a2b0 (bf16 path)
#define DO_TERMS_N(ACCSEL, NT)                                               \
    {                                                                        \
        constexpr int TA[6] = {0, 0, 1, 1, 0, 2};                            \
        constexpr int TB[6] = {0, 1, 0, 1, 2, 0};                            \
        _Pragma("unroll")                                                    \
        for (int t = 0; t < (NT); t++) {                                     \
            const int ap = TA[t], bp = TB[t];                                \
            _Pragma("unroll")                                                \
            for (int q = 0; q < 2; q++)                                      \
                _Pragma("unroll")                                            \
                for (int sub = 0; sub < 2; sub++)                            \
                    _Pragma("unroll")                                        \
                    for (int mt = 0; mt < 2; mt++)                           \
                        mma16(F.acc[mt][ACCSEL],                             \
                              Af[mt][ap], Bm[q][bp][sub], Bm[q][bp][sub+2]); \
        }                                                                    \
    }

// Stage loader: NPL planes per chunk, CHS = global chunk stride in shorts.
// R12 mapping: threads t..t+SEGS-1 cover one contiguous row-chunk (coalesced).
template<int NPL, int CHS>
__device__ __forceinline__ void ld_stage(
    ushort_t* sm, int stage,
    const ushort_t* __restrict__ A, int lda,
    const ushort_t* __restrict__ B, int ldb, int kt)
{
    constexpr int SEGS = 2 * NPL;
    constexpr int TOT  = 2 * 128 * SEGS;
#pragma unroll
    for (int t = threadIdx.x; t < TOT; t += 256) {
        const int side = (t >= TOT / 2) ? 1 : 0;
        const int r    = side ? (t - TOT / 2) : t;
        const int row  = r / SEGS;
        const int seg  = r - row * SEGS;
        const int p    = seg >> 1;
        const int half = seg & 1;
        const ushort_t* src = (side ? B + (size_t)row * ldb
                                    : A + (size_t)row * lda) + kt * CHS + seg * 8;
        uint32_t dst = s2u(&sm[side * SOP + ((stage * 3 + p) * 128 + row) * SROW + half * 8]);
        cp16cg(dst, src);
    }
}

template<int NTERMS>
__device__ __forceinline__ void gemm_planes(
    ushort_t* sm,
    const ushort_t* __restrict__ A, int lda,
    const ushort_t* __restrict__ B, int ldb,
    int NK, Frag& F)
{
    constexpr int NPL = (NTERMS >= 4) ? 3 : ((NTERMS == 1) ? 1 : 2);
    constexpr int CHS = (NTERMS == 1) ? 16 : 48;

    const int tid  = threadIdx.x;
    const int lane = tid & 31;
    const int wid  = tid >> 5;
    const int wm   = wid & 3;
    const int wn   = wid >> 2;

    const int lrow = (lane & 7) + ((lane >> 3) & 1) * 8;
    const int lhal = lane >> 4;

    const uint32_t smb = s2u(sm);
    uint32_t aoff[2], boff[4];
#pragma unroll
    for (int mt = 0; mt < 2; mt++)
        aoff[mt] = smb + ((wm * 32 + mt * 16 + lrow) * SROW + lhal * 8) * 2;
#pragma unroll
    for (int ntp = 0; ntp < 4; ntp++)
        boff[ntp] = smb + SOP * 2 + ((wn * 64 + ntp * 16 + lrow) * SROW + lhal * 8) * 2;

#pragma unroll
    for (int mt = 0; mt < 2; mt++)
#pragma unroll
        for (int nt = 0; nt < 8; nt++)
#pragma unroll
            for (int r = 0; r < 4; r++) F.acc[mt][nt][r] = 0.f;

#pragma unroll
    for (int p = 0; p < NSTG - 1; p++) {
        ld_stage<NPL, CHS>(sm, p, A, lda, B, ldb, p);
        CP_COMMIT();
    }

    for (int kt = 0; kt < NK; kt++) {
        const bool more = (kt + NSTG - 1 < NK);
        if (more) { CP_WAIT(1); } else { CP_WAIT(0); }
        __syncthreads();
        if (more) {
            ld_stage<NPL, CHS>(sm, (kt + NSTG - 1) % NSTG, A, lda, B, ldb, kt + NSTG - 1);
            CP_COMMIT();
        }

        const int buf = kt % 3;
        const uint32_t pbase = (uint32_t)(buf * 3) * SPL * 2;

        uint32_t Af[2][3][4];
#pragma unroll
        for (int mt = 0; mt < 2; mt++)
#pragma unroll
            for (int p = 0; p < NPL; p++)
                ldsm4(Af[mt][p][0], Af[mt][p][1], Af[mt][p][2], Af[mt][p][3],
                      aoff[mt] + pbase + p * SPL * 2);

#pragma unroll
        for (int hp = 0; hp < 2; hp++) {
            uint32_t Bm[2][3][4];
#pragma unroll
            for (int q = 0; q < 2; q++)
#pragma unroll
                for (int p = 0; p < NPL; p++)
                    ldsm4(Bm[q][p][0], Bm[q][p][1], Bm[q][p][2], Bm[q][p][3],
                          boff[hp * 2 + q] + pbase + p * SPL * 2);
            if constexpr (NTERMS == 1) {
#pragma unroll
                for (int q = 0; q < 2; q++)
#pragma unroll
                    for (int sub = 0; sub < 2; sub++)
#pragma unroll
                        for (int mt = 0; mt < 2; mt++)
                            mma16h(F.acc[mt][(hp * 2 + q) * 2 + sub],
                                   Af[mt][0], Bm[q][0][sub], Bm[q][0][sub + 2]);
            } else {
                DO_TERMS_N((hp * 2 + q) * 2 + sub, NTERMS)
            }
        }
    }
    __syncthreads();
}

// ---------------------------------------------------------------------------
// Kernel 1: proj  Y[4096,3072] = x @ [Wq;Wkv]^T
// q/k tiles: 6 bf16 terms (bit-exact, feeds argmax).
// v tiles: plain fp16 (1 term, ~3e-4 rel err; values only, no argmax role).
// ---------------------------------------------------------------------------
__global__ __launch_bounds__(256, 2) void proj_tc()
{
    extern __shared__ __align__(16) ushort_t smp[];

    const int m0 = blockIdx.y * 128;
    const int n0 = blockIdx.x * 128;
    const bool isv = (n0 >= 2048);

    Frag F;
    if (isv)
        gemm_planes<1>(smp, g_xh + (size_t)m0 * 1024, 1024,
                       g_wh + (size_t)(n0 - 2048) * 1024, 1024, 64, F);
    else
        gemm_planes<6>(smp, g_x3 + (size_t)m0 * 3072, 3072,
                       g_w3 + (size_t)n0 * 3072, 3072, 64, F);

    const int lane = threadIdx.x & 31;
    const int wid  = threadIdx.x >> 5;
    const int wm = wid & 3, wn = wid >> 2;

#pragma unroll
    for (int mt = 0; mt < 2; mt++)
#pragma unroll
        for (int nt = 0; nt < 8; nt++) {
            const int r  = m0 + wm * 32 + mt * 16 + (lane >> 2);
            const int cc = n0 + wn * 64 + nt * 8 + (lane & 3) * 2;
            const float* c = F.acc[mt][nt];
            if (isv) {
                *(float2*)(g_v + (size_t)r * 1024 + (cc - 2048)) = make_float2(c[0], c[1]);
                *(float2*)(g_v + (size_t)(r + 8) * 1024 + (cc - 2048)) = make_float2(c[2], c[3]);
            } else {
                const bool isq = (n0 < 1024);
                const int nn = isq ? cc : cc - 1024;
                const int h = nn >> 6, d = nn & 63;
                const int bidx = r >> 10;
                ushort_t* cat = isq ? g_q3 : g_k3;
                const size_t row0 = (size_t)(bidx * 16 + h) * 1024 + (r & 1023);
                const size_t row1 = (size_t)(bidx * 16 + h) * 1024 + ((r + 8) & 1023);
                store3(cat, row0, 4, d, c[0], c[1]);
                store3(cat, row1, 4, d, c[2], c[3]);
            }
        }
}

// ---------------------------------------------------------------------------
// Kernel 2: score  S[b,h] = (q_h k_h^T)/32   [R12 verbatim — bit-exact]
// ---------------------------------------------------------------------------
__device__ __forceinline__ void ld_Bstage(
    ushort_t* smB, int stage, const ushort_t* __restrict__ B, int kt)
{
#pragma unroll
    for (int t = threadIdx.x; t < 768; t += 256) {
        const int row  = t / 6;
        const int seg  = t - row * 6;
        const int p    = seg >> 1;
        const int half = seg & 1;
        cp16cg(s2u(&smB[((stage * 3 + p) * 128 + row) * SROW + half * 8]),
               B + (size_t)row * 192 + kt * 48 + seg * 8);
    }
}

__global__ __launch_bounds__(256, 2) void score_tc()
{
    extern __shared__ __align__(16) ushort_t smp[];
    ushort_t* smA = smp;                 // [4 chunks][3 planes][128][SROW]
    ushort_t* smB = smp + 12 * SPL;      // [2 stages][3 planes][128][SROW]

    const int jt0 = blockIdx.x * 4;
    const int it  = blockIdx.y;
    const int z   = blockIdx.z;

    const ushort_t* Ab = g_q3 + ((size_t)z * 1024 + it * 128) * 192;
    const ushort_t* Bz = g_k3 + (size_t)z * 1024 * 192;

    for (int t = threadIdx.x; t < 3072; t += 256) {
        const int c    = t / 768;
        const int rr   = t - c * 768;
        const int row  = rr / 6;
        const int seg  = rr - row * 6;
        const int p    = seg >> 1;
        const int half = seg & 1;
        cp16cg(s2u(&smA[((c * 3 + p) * 128 + row) * SROW + half * 8]),
               Ab + (size_t)row * 192 + c * 48 + seg * 8);
    }
    ld_Bstage(smB, 0, Bz + (size_t)(jt0 * 128) * 192, 0);
    CP_COMMIT();

    const int tid  = threadIdx.x;
    const int lane = tid & 31;
    const int wid  = tid >> 5;
    const int wm   = wid & 3;
    const int wn   = wid >> 2;
    const int lrow = (lane & 7) + ((lane >> 3) & 1) * 8;
    const int lhal = lane >> 4;

    uint32_t aoff[2], boff[4];
#pragma unroll
    for (int mt = 0; mt < 2; mt++)
        aoff[mt] = s2u(smA) + ((wm * 32 + mt * 16 + lrow) * SROW + lhal * 8) * 2;
#pragma unroll
    for (int ntp = 0; ntp < 4; ntp++)
        boff[ntp] = s2u(smB) + ((wn * 64 + ntp * 16 + lrow) * SROW + lhal * 8) * 2;

    Frag F;
#pragma unroll
    for (int mt = 0; mt < 2; mt++)
#pragma unroll
        for (int nt = 0; nt < 8; nt++)
#pragma unroll
            for (int r = 0; r < 4; r++) F.acc[mt][nt][r] = 0.f;

    const float scale = 0.03125f;

    for (int s = 0; s < 16; s++) {
        CP_WAIT(0);
        __syncthreads();
        if (s + 1 < 16) {
            const int jtn = jt0 + (s + 1) / 4;
            const int ktn = (s + 1) & 3;
            ld_Bstage(smB, (s + 1) & 1, Bz + (size_t)(jtn * 128) * 192, ktn);
            CP_COMMIT();
        }

        const int kt = s & 3;
        const uint32_t abase = (uint32_t)(kt * 3) * SPL * 2;
        const uint32_t bbase = (uint32_t)((s & 1) * 3) * SPL * 2;

        uint32_t Af[2][3][4];
#pragma unroll
        for (int mt = 0; mt < 2; mt++)
#pragma unroll
            for (int p = 0; p < 3; p++)
                ldsm4(Af[mt][p][0], Af[mt][p][1], Af[mt][p][2], Af[mt][p][3],
                      aoff[mt] + abase + p * SPL * 2);

#pragma unroll
        for (int hp = 0; hp < 2; hp++) {
            uint32_t Bm[2][3][4];
#pragma unroll
            for (int q = 0; q < 2; q++)
#pragma unroll
                for (int p = 0; p < 3; p++)
                    ldsm4(Bm[q][p][0], Bm[q][p][1], Bm[q][p][2], Bm[q][p][3],
                          boff[hp * 2 + q] + bbase + p * SPL * 2);
            DO_TERMS_N((hp * 2 + q) * 2 + sub, 6)
        }

        if (kt == 3) {
            const int jt = jt0 + (s >> 2);
#pragma unroll
            for (int mt = 0; mt < 2; mt++)
#pragma unroll
                for (int nt = 0; nt < 8; nt++) {
                    int r  = it * 128 + wm * 32 + mt * 16 + (lane >> 2);
                    int cc = jt * 128 + wn * 64 + nt * 8 + (lane & 3) * 2;
                    float* base = g_s + ((size_t)z * Nn + r) * Nn + cc;
                    float* c = F.acc[mt][nt];
                    __stcs((float2*)base, make_float2(c[0] * scale, c[1] * scale));
                    __stcs((float2*)(base + 8 * Nn), make_float2(c[2] * scale, c[3] * scale));
                    c[0] = 0.f; c[1] = 0.f; c[2] = 0.f; c[3] = 0.f;
                }
        }
    }
}

// ---------------------------------------------------------------------------
// Kernel 3: attn — R12 version (unchanged).
// ---------------------------------------------------------------------------
__global__ __launch_bounds__(512) void attn_kernel(
    const float* __restrict__ Wt,
    const float* __restrict__ ln_g,
    const float* __restrict__ ln_b,
    float* __restrict__ out)
{
    extern __shared__ float sm[];
    float* sw   = sm;                 // [16][1024] raw exp values
    float* swt  = sm + Hn * Nn;       // [256]
    float* sg   = swt + 256;          // [16]
    float* sb   = sg + 16;            // [16]
    float* ssum = sb + 16;            // [16]

    const int tid = threadIdx.x;
    const int i   = blockIdx.x;
    const int b   = blockIdx.y;

#pragma unroll
    for (int f = tid; f < Hn * Nn / 4; f += 512) {
        int h = f >> 8;
        int j4 = (f & 255) * 4;
        cp16cg(s2u(sw + h * Nn + j4),
               g_s + ((size_t)(b * Hn + h) * Nn + i) * Nn + j4);
    }
    CP_COMMIT();
    if (tid < 256) swt[tid] = Wt[tid];
    if (tid < 16) { sg[tid] = ln_g[tid]; sb[tid] = ln_b[tid]; }
    CP_WAIT(0);
    __syncthreads();

    const int warp = tid >> 5;
    const int lane = tid & 31;

    {
        float* row = sw + warp * Nn;
        float m = -INFINITY;
        for (int j = lane; j < Nn; j += 32) m = fmaxf(m, row[j]);
#pragma unroll
        for (int o = 16; o; o >>= 1) m = fmaxf(m, __shfl_xor_sync(~0u, m, o));
        float s = 0.f;
        for (int j = lane; j < Nn; j += 32) { float e = expf(row[j] - m); row[j] = e; s += e; }
#pragma unroll
        for (int o = 16; o; o >>= 1) s += __shfl_xor_sync(~0u, s, o);
        if (lane == 0) ssum[warp] = s;
    }
    __syncthreads();

    for (int j = tid; j < Nn; j += 512) {
        float wc[16];
#pragma unroll
        for (int h = 0; h < 16; h++) wc[h] = sw[h * Nn + j] / ssum[h];
        float mix[16];
        float mu = 0.f;
#pragma unroll
        for (int ho = 0; ho < 16; ho++) {
            float acc = 0.f;
#pragma unroll
            for (int h = 0; h < 16; h++) acc += swt[ho * 16 + h] * wc[h];
            mix[ho] = acc;
            mu += acc;
        }
        mu *= (1.f / 16.f);
        float var = 0.f;
#pragma unroll
        for (int ho = 0; ho < 16; ho++) { float d = mix[ho] - mu; var += d * d; }
        var *= (1.f / 16.f);
        const float denom = sqrtf(var + 1e-5f);
#pragma unroll
        for (int ho = 0; ho < 16; ho++)
            sw[ho * Nn + j] = (mix[ho] - mu) / denom * sg[ho] + sb[ho];
    }
    __syncthreads();

    {
        const int h = warp;
        float* row = sw + h * Nn;
        float bv = -INFINITY;
        int   bi = 0;
        for (int j = lane; j < Nn; j += 32) {
            float v = row[j];
            if (v > bv) { bv = v; bi = j; }
        }
#pragma unroll
        for (int o = 16; o; o >>= 1) {
            float ov = __shfl_xor_sync(~0u, bv, o);
            int   oi = __shfl_xor_sync(~0u, bi, o);
            if (ov > bv || (ov == bv && oi < bi)) { bv = ov; bi = oi; }
        }
        const float* vsrc = g_v + (size_t)(b * Nn + bi) * 1024 + h * DHn;
        float* dst = out + (size_t)(b * Nn + i) * Dn + h * DHn;
#pragma unroll
        for (int d = lane; d < DHn; d += 32) dst[d] = vsrc[d];
    }
}

// ---------------------------------------------------------------------------
extern "C" void kernel_launch(void* const* d_in, const int* in_sizes, int n_in,
                              void* d_out, int out_size)
{
    const float* x    = (const float*)d_in[0];
    const float* Wq   = (const float*)d_in[1];
    const float* Wkv  = (const float*)d_in[2];
    const float* Wt   = (const float*)d_in[3];
    const float* ln_g = (const float*)d_in[4];
    const float* ln_b = (const float*)d_in[5];
    float* out = (float*)d_out;

    const int total = (4096 + 3072) * 512;
    prep_kernel<<<(total + 255) / 256, 256>>>(x, Wq, Wkv);

    cudaFuncSetAttribute(proj_tc, cudaFuncAttributeMaxDynamicSharedMemorySize, SMEMB);
    cudaFuncSetAttribute(score_tc, cudaFuncAttributeMaxDynamicSharedMemorySize, SMEMB);

    proj_tc<<<dim3(3072 / 128, 4096 / 128), 256, SMEMB>>>();
    score_tc<<<dim3(Nn / 512, Nn / 128, Bn * Hn), 256, SMEMB>>>();

    const int asmem = (Hn * Nn + 256 + 16 + 16 + 16) * sizeof(float);
    cudaFuncSetAttribute(attn_kernel, cudaFuncAttributeMaxDynamicSharedMemorySize, asmem);
    attn_kernel<<<dim3(Nn, Bn), 512, asmem>>>(Wt, ln_g, ln_b, out);
}